// round 1
// baseline (speedup 1.0000x reference)
#include <cuda_runtime.h>
#include <math.h>

// Problem constants
#define Bb   4
#define Ss   2048
#define HIDn 1024
#define HEADS 16
#define HD   64
#define ROWS (Bb*Ss)          // 8192

// ---------------- scratch (device globals: allocation-guard safe) ----------
__device__ float g_Q[Bb*HEADS*Ss*HD];   // [B,H,S,D]
__device__ float g_K[Bb*HEADS*Ss*HD];
__device__ float g_V[Bb*HEADS*Ss*HD];
__device__ float g_O[Bb*Ss*HIDn];       // [B,S,H*D] row-major

// ============================================================================
// GEMM: C = A[M,K] * W[K,N] + bias[N]
// MODE 0: C row-major [M,N]
// MODE 1: scatter to [B,H,S,D]: row=(b,s), col=(h,d)
// Tiles: BM=BN=128, BK=16, 256 threads, 8x8 per thread.
// ============================================================================
#define GBM 128
#define GBN 128
#define GBK 16

template<int MODE>
__global__ __launch_bounds__(256)
void gemm_bias(const float* __restrict__ A, const float* __restrict__ W,
               const float* __restrict__ bias, float* __restrict__ C,
               int M, int N, int K)
{
    __shared__ float As[GBK][GBM + 4];   // transposed, padded (2-way max)
    __shared__ float Bs[GBK][GBN];

    const int tid = threadIdx.x;
    const int tx  = tid & 15;            // 0..15 -> 8 cols each
    const int ty  = tid >> 4;            // 0..15 -> 8 rows each
    const int row0 = blockIdx.y * GBM;
    const int col0 = blockIdx.x * GBN;

    float acc[8][8];
    #pragma unroll
    for (int i = 0; i < 8; i++)
        #pragma unroll
        for (int j = 0; j < 8; j++) acc[i][j] = 0.f;

    for (int kt = 0; kt < K; kt += GBK) {
        // load A tile 128x16 (512 float4, 2 per thread), store transposed
        #pragma unroll
        for (int l = 0; l < 2; l++) {
            int f  = tid + l * 256;
            int ar = f >> 2;
            int ac = (f & 3) << 2;
            float4 v = *(const float4*)(A + (size_t)(row0 + ar) * K + kt + ac);
            As[ac + 0][ar] = v.x;
            As[ac + 1][ar] = v.y;
            As[ac + 2][ar] = v.z;
            As[ac + 3][ar] = v.w;
        }
        // load W tile 16x128 (512 float4, 2 per thread), direct
        #pragma unroll
        for (int l = 0; l < 2; l++) {
            int f  = tid + l * 256;
            int br = f >> 5;
            int bc = (f & 31) << 2;
            *(float4*)&Bs[br][bc] =
                *(const float4*)(W + (size_t)(kt + br) * N + col0 + bc);
        }
        __syncthreads();

        #pragma unroll
        for (int k = 0; k < GBK; k++) {
            float a[8], b[8];
            *(float4*)&a[0] = *(float4*)&As[k][ty * 8];
            *(float4*)&a[4] = *(float4*)&As[k][ty * 8 + 4];
            *(float4*)&b[0] = *(float4*)&Bs[k][tx * 8];
            *(float4*)&b[4] = *(float4*)&Bs[k][tx * 8 + 4];
            #pragma unroll
            for (int i = 0; i < 8; i++)
                #pragma unroll
                for (int j = 0; j < 8; j++)
                    acc[i][j] = fmaf(a[i], b[j], acc[i][j]);
        }
        __syncthreads();
    }

    // epilogue
    #pragma unroll
    for (int i = 0; i < 8; i++) {
        int gr = row0 + ty * 8 + i;
        #pragma unroll
        for (int j = 0; j < 8; j++) {
            int gc = col0 + tx * 8 + j;
            float v = acc[i][j] + bias[gc];
            if (MODE == 0) {
                C[(size_t)gr * N + gc] = v;
            } else {
                int b = gr >> 11;        // /2048
                int s = gr & 2047;
                int h = gc >> 6;         // /64
                int d = gc & 63;
                C[(((size_t)(b * HEADS + h)) * Ss + s) * HD + d] = v;
            }
        }
    }
}

// ============================================================================
// Flash attention (fp32): one block = one (bh, 128-query tile).
// K-tiles of 128. Online softmax. Writes g_O in [B,S,H*D].
// smem: Qs[128][65], Ks[128][65], Vs[128][68], Ps[128][129], m/l/c[128]
// ============================================================================
#define QS_STR 65
#define VS_STR 68
#define PS_STR 129
#define ATT_SMEM_FLOATS (128*QS_STR + 128*QS_STR + 128*VS_STR + 128*PS_STR + 3*128)
#define ATT_SMEM_BYTES  (ATT_SMEM_FLOATS * 4)

__global__ __launch_bounds__(256)
void attn_kernel()
{
    extern __shared__ float sm[];
    float* Qs   = sm;                         // 128*65
    float* Ks   = Qs + 128 * QS_STR;          // 128*65
    float* Vs   = Ks + 128 * QS_STR;          // 128*68
    float* Ps   = Vs + 128 * VS_STR;          // 128*129
    float* mrow = Ps + 128 * PS_STR;          // 128
    float* lrow = mrow + 128;
    float* crow = lrow + 128;

    const int bh  = blockIdx.y;               // 0..63
    const int qt  = blockIdx.x;               // 0..15
    const int tid = threadIdx.x;
    const int tx  = tid & 15;                 // dims tx*4 .. tx*4+3
    const int ty  = tid >> 4;                 // rows ty*8 .. ty*8+7

    const float* Qg = g_Q + (size_t)bh * Ss * HD + (size_t)qt * 128 * HD;
    const float* Kg = g_K + (size_t)bh * Ss * HD;
    const float* Vg = g_V + (size_t)bh * Ss * HD;

    // load Q tile (128x64), scalar stores into padded smem
    for (int f = tid; f < 2048; f += 256) {
        int r  = f >> 4;
        int c4 = (f & 15) << 2;
        float4 v = *(const float4*)(Qg + (size_t)r * HD + c4);
        float* q = Qs + r * QS_STR + c4;
        q[0] = v.x; q[1] = v.y; q[2] = v.z; q[3] = v.w;
    }
    if (tid < 128) { mrow[tid] = -1e30f; lrow[tid] = 0.f; }

    float o[8][4];
    #pragma unroll
    for (int i = 0; i < 8; i++)
        #pragma unroll
        for (int j = 0; j < 4; j++) o[i][j] = 0.f;

    for (int kt = 0; kt < 16; kt++) {
        __syncthreads();   // prev PV reads done before overwriting K/V

        const float* Kt = Kg + (size_t)kt * 128 * HD;
        const float* Vt = Vg + (size_t)kt * 128 * HD;
        for (int f = tid; f < 2048; f += 256) {
            int r  = f >> 4;
            int c4 = (f & 15) << 2;
            float4 kv = *(const float4*)(Kt + (size_t)r * HD + c4);
            float* kp = Ks + r * QS_STR + c4;
            kp[0] = kv.x; kp[1] = kv.y; kp[2] = kv.z; kp[3] = kv.w;
            float4 vv = *(const float4*)(Vt + (size_t)r * HD + c4);
            float* vp = Vs + r * VS_STR + c4;
            vp[0] = vv.x; vp[1] = vv.y; vp[2] = vv.z; vp[3] = vv.w;
        }
        __syncthreads();

        // scores: 128x128x64, 8x8 per thread
        float sacc[8][8];
        #pragma unroll
        for (int i = 0; i < 8; i++)
            #pragma unroll
            for (int j = 0; j < 8; j++) sacc[i][j] = 0.f;

        #pragma unroll 4
        for (int kd = 0; kd < HD; kd++) {
            float qv[8], kv[8];
            #pragma unroll
            for (int i = 0; i < 8; i++) qv[i] = Qs[(ty * 8 + i) * QS_STR + kd];
            #pragma unroll
            for (int j = 0; j < 8; j++) kv[j] = Ks[(tx * 8 + j) * QS_STR + kd];
            #pragma unroll
            for (int i = 0; i < 8; i++)
                #pragma unroll
                for (int j = 0; j < 8; j++)
                    sacc[i][j] = fmaf(qv[i], kv[j], sacc[i][j]);
        }
        #pragma unroll
        for (int i = 0; i < 8; i++)
            #pragma unroll
            for (int j = 0; j < 8; j++)
                Ps[(ty * 8 + i) * PS_STR + tx * 8 + j] = sacc[i][j] * 0.125f;
        __syncthreads();

        // online softmax per row (stride-129 -> conflict-free column scan)
        if (tid < 128) {
            float* pr = Ps + tid * PS_STR;
            float mx = mrow[tid];
            #pragma unroll 4
            for (int k = 0; k < 128; k++) mx = fmaxf(mx, pr[k]);
            float corr = __expf(mrow[tid] - mx);
            float sum  = lrow[tid] * corr;
            #pragma unroll 4
            for (int k = 0; k < 128; k++) {
                float p = __expf(pr[k] - mx);
                pr[k] = p;
                sum  += p;
            }
            mrow[tid] = mx;
            lrow[tid] = sum;
            crow[tid] = corr;
        }
        __syncthreads();

        // rescale accumulators and accumulate P @ V
        #pragma unroll
        for (int i = 0; i < 8; i++) {
            float c = crow[ty * 8 + i];
            #pragma unroll
            for (int j = 0; j < 4; j++) o[i][j] *= c;
        }
        #pragma unroll 2
        for (int k = 0; k < 128; k++) {
            float4 vv = *(const float4*)(Vs + k * VS_STR + tx * 4);
            #pragma unroll
            for (int i = 0; i < 8; i++) {
                float p = Ps[(ty * 8 + i) * PS_STR + k];
                o[i][0] = fmaf(p, vv.x, o[i][0]);
                o[i][1] = fmaf(p, vv.y, o[i][1]);
                o[i][2] = fmaf(p, vv.z, o[i][2]);
                o[i][3] = fmaf(p, vv.w, o[i][3]);
            }
        }
    }

    // normalize + store to g_O [B,S,H*D]
    const int b = bh >> 4;
    const int h = bh & 15;
    #pragma unroll
    for (int i = 0; i < 8; i++) {
        int r   = ty * 8 + i;
        int s   = qt * 128 + r;
        float inv = 1.0f / lrow[r];
        float4 out;
        out.x = o[i][0] * inv;
        out.y = o[i][1] * inv;
        out.z = o[i][2] * inv;
        out.w = o[i][3] * inv;
        size_t idx = ((size_t)(b * Ss + s)) * HIDn + h * HD + tx * 4;
        *(float4*)(g_O + idx) = out;
    }
}

// ============================================================================
// launch
// ============================================================================
extern "C" void kernel_launch(void* const* d_in, const int* in_sizes, int n_in,
                              void* d_out, int out_size)
{
    (void)in_sizes; (void)n_in; (void)out_size;
    const float* q  = (const float*)d_in[0];
    const float* k  = (const float*)d_in[1];
    const float* v  = (const float*)d_in[2];
    const float* wq = (const float*)d_in[3];
    const float* bq = (const float*)d_in[4];
    const float* wk = (const float*)d_in[5];
    const float* bk = (const float*)d_in[6];
    const float* wv = (const float*)d_in[7];
    const float* bv = (const float*)d_in[8];
    const float* wo = (const float*)d_in[9];
    const float* bo = (const float*)d_in[10];
    float* out = (float*)d_out;

    float *Qp, *Kp, *Vp, *Op;
    cudaGetSymbolAddress((void**)&Qp, g_Q);
    cudaGetSymbolAddress((void**)&Kp, g_K);
    cudaGetSymbolAddress((void**)&Vp, g_V);
    cudaGetSymbolAddress((void**)&Op, g_O);

    cudaFuncSetAttribute(attn_kernel,
                         cudaFuncAttributeMaxDynamicSharedMemorySize,
                         ATT_SMEM_BYTES);

    dim3 ggrid(HIDn / GBN, ROWS / GBM);   // (8, 64)

    gemm_bias<1><<<ggrid, 256>>>(q, wq, bq, Qp, ROWS, HIDn, HIDn);
    gemm_bias<1><<<ggrid, 256>>>(k, wk, bk, Kp, ROWS, HIDn, HIDn);
    gemm_bias<1><<<ggrid, 256>>>(v, wv, bv, Vp, ROWS, HIDn, HIDn);

    attn_kernel<<<dim3(Ss / 128, Bb * HEADS), 256, ATT_SMEM_BYTES>>>();

    gemm_bias<0><<<ggrid, 256>>>(Op, wo, bo, out, ROWS, HIDn, HIDn);
}

// round 3
// speedup vs baseline: 2.5253x; 2.5253x over previous
#include <cuda_runtime.h>
#include <math.h>
#include <stdint.h>

// Problem constants
#define Bb   4
#define Ss   2048
#define HIDn 1024
#define HEADS 16
#define HD   64
#define ROWS (Bb*Ss)          // 8192

// ---------------- scratch (device globals: allocation-guard safe) ----------
__device__ float g_Q[Bb*HEADS*Ss*HD];   // [B,H,S,D] (tf32-rounded)
__device__ float g_K[Bb*HEADS*Ss*HD];
__device__ float g_V[Bb*HEADS*Ss*HD];
__device__ float g_O[Bb*Ss*HIDn];       // [B,S,H*D] row-major (fp32)
__device__ float g_WT[HIDn*HIDn];       // transposed + tf32-rounded weight

// ============================================================================
// helpers
// ============================================================================
__device__ __forceinline__ uint32_t smem_u32(const void* p) {
    uint32_t a;
    asm("{ .reg .u64 t; cvta.to.shared.u64 t, %1; cvt.u32.u64 %0, t; }"
        : "=r"(a) : "l"(p));
    return a;
}
__device__ __forceinline__ uint32_t f2tf(float x) {
    uint32_t u;
    asm("cvt.rna.tf32.f32 %0, %1;" : "=r"(u) : "f"(x));
    return u;
}
__device__ __forceinline__ float tf32r(float x) { return __uint_as_float(f2tf(x)); }

__device__ __forceinline__ void mma8(float& d0, float& d1, float& d2, float& d3,
                                     uint32_t a0, uint32_t a1, uint32_t a2, uint32_t a3,
                                     uint32_t b0, uint32_t b1) {
    asm volatile(
        "mma.sync.aligned.m16n8k8.row.col.f32.tf32.tf32.f32 "
        "{%0,%1,%2,%3}, {%4,%5,%6,%7}, {%8,%9}, {%0,%1,%2,%3};"
        : "+f"(d0), "+f"(d1), "+f"(d2), "+f"(d3)
        : "r"(a0), "r"(a1), "r"(a2), "r"(a3), "r"(b0), "r"(b1));
}
__device__ __forceinline__ void cp16(uint32_t s, const void* g) {
    asm volatile("cp.async.cg.shared.global [%0], [%1], 16;" :: "r"(s), "l"(g));
}
#define CP_COMMIT() asm volatile("cp.async.commit_group;" ::: "memory")
#define CP_WAIT1()  asm volatile("cp.async.wait_group 1;"  ::: "memory")

// ============================================================================
// Weight transpose + tf32 rounding: WT[n][k] = tf32(W[k][n])
// ============================================================================
__global__ __launch_bounds__(256)
void transpose1024(const float* __restrict__ in, float* __restrict__ out)
{
    __shared__ float t[32][33];
    int x = blockIdx.x * 32 + threadIdx.x;
    int y0 = blockIdx.y * 32;
    #pragma unroll
    for (int l = 0; l < 32; l += 8)
        t[threadIdx.y + l][threadIdx.x] = in[(size_t)(y0 + threadIdx.y + l) * 1024 + x];
    __syncthreads();
    int xo = blockIdx.y * 32 + threadIdx.x;
    int yo = blockIdx.x * 32;
    #pragma unroll
    for (int l = 0; l < 32; l += 8)
        out[(size_t)(yo + threadIdx.y + l) * 1024 + xo] = tf32r(t[threadIdx.x][threadIdx.y + l]);
}

// ============================================================================
// tf32 mma.sync GEMM: C = A[M,1024] * W[1024,N] + bias,  W pre-transposed
// (WT[N,1024], K-major, tf32-rounded). 128x128 tile/CTA, BK=32, 3-stage
// cp.async. 8 warps, warp tile 64x32 (wm=wid&1, wn=wid>>1).
// MODE 0: C row-major [M,N] fp32.  MODE 1: scatter to [B,H,S,D], tf32-rounded.
// ============================================================================
#define GSTAGES 3
#define GASTR   36
#define GSTG    (128*GASTR)            // floats per stage per tensor
#define GEMM_SMEM (2*GSTAGES*GSTG*4)   // bytes

template<int MODE>
__global__ __launch_bounds__(256, 1)
void gemm_tc(const float* __restrict__ A, const float* __restrict__ WT,
             const float* __restrict__ bias, float* __restrict__ C)
{
    extern __shared__ float smf[];
    float* As = smf;                    // [3][128][36]
    float* Bs = smf + GSTAGES * GSTG;   // [3][128][36]
    const uint32_t sA = smem_u32(As);
    const uint32_t sB = smem_u32(Bs);

    const int tid  = threadIdx.x;
    const int wid  = tid >> 5;
    const int lane = tid & 31;
    const int gr   = lane >> 2;
    const int tc   = lane & 3;
    const int wm   = wid & 1;          // 2 row groups of 64
    const int wn   = wid >> 1;         // 4 col groups of 32
    const int row0 = blockIdx.y * 128;
    const int col0 = blockIdx.x * 128;

    const float* Ag0 = A  + (size_t)row0 * 1024;
    const float* Bg0 = WT + (size_t)col0 * 1024;

    float acc[4][4][4];
    #pragma unroll
    for (int mt = 0; mt < 4; mt++)
        #pragma unroll
        for (int nt = 0; nt < 4; nt++)
            #pragma unroll
            for (int e = 0; e < 4; e++) acc[mt][nt][e] = 0.f;

    // stage loader: 128 rows x 32 floats each for A and B
    const int lr  = tid >> 3;          // base row pattern (with +32*l)
    const int lc4 = tid & 7;
    #define LOAD_STAGE(st, chunk) do {                                         \
        const float* _Ag = Ag0 + (chunk) * 32;                                 \
        const float* _Bg = Bg0 + (chunk) * 32;                                 \
        uint32_t _aS = sA + (st) * GSTG * 4;                                   \
        uint32_t _bS = sB + (st) * GSTG * 4;                                   \
        _Pragma("unroll")                                                      \
        for (int l = 0; l < 4; l++) {                                          \
            int r = lr + l * 32;                                               \
            cp16(_aS + r * 144 + lc4 * 16, _Ag + (size_t)r * 1024 + lc4 * 4);  \
            cp16(_bS + r * 144 + lc4 * 16, _Bg + (size_t)r * 1024 + lc4 * 4);  \
        }                                                                      \
    } while (0)

    LOAD_STAGE(0, 0); CP_COMMIT();
    LOAD_STAGE(1, 1); CP_COMMIT();

    for (int i = 0; i < 32; i++) {
        const int s = i % 3;
        CP_WAIT1();
        __syncthreads();

        const float* Asb = As + s * GSTG;
        const float* Bsb = Bs + s * GSTG;

        #pragma unroll
        for (int ks = 0; ks < 4; ks++) {
            const int k0 = ks * 8;
            uint32_t a[4][4], b[4][2];
            #pragma unroll
            for (int mt = 0; mt < 4; mt++) {
                const float* p = Asb + (wm * 64 + mt * 16 + gr) * GASTR + k0 + tc;
                a[mt][0] = f2tf(p[0]);
                a[mt][1] = f2tf(p[8 * GASTR]);
                a[mt][2] = f2tf(p[4]);
                a[mt][3] = f2tf(p[8 * GASTR + 4]);
            }
            #pragma unroll
            for (int nt = 0; nt < 4; nt++) {
                const float* p = Bsb + (wn * 32 + nt * 8 + gr) * GASTR + k0 + tc;
                b[nt][0] = __float_as_uint(p[0]);   // pre-rounded
                b[nt][1] = __float_as_uint(p[4]);
            }
            #pragma unroll
            for (int mt = 0; mt < 4; mt++)
                #pragma unroll
                for (int nt = 0; nt < 4; nt++)
                    mma8(acc[mt][nt][0], acc[mt][nt][1], acc[mt][nt][2], acc[mt][nt][3],
                         a[mt][0], a[mt][1], a[mt][2], a[mt][3], b[nt][0], b[nt][1]);
        }

        const int j = i + 2;
        if (j < 32) { LOAD_STAGE(j % 3, j); }
        CP_COMMIT();
    }

    // ---- epilogue ----
    #pragma unroll
    for (int mt = 0; mt < 4; mt++) {
        const int r0 = row0 + wm * 64 + mt * 16 + gr;
        #pragma unroll
        for (int nt = 0; nt < 4; nt++) {
            const int c = col0 + wn * 32 + nt * 8 + 2 * tc;
            const float2 bi = *(const float2*)(bias + c);
            float v00 = acc[mt][nt][0] + bi.x, v01 = acc[mt][nt][1] + bi.y;
            float v10 = acc[mt][nt][2] + bi.x, v11 = acc[mt][nt][3] + bi.y;
            if (MODE == 1) {
                v00 = tf32r(v00); v01 = tf32r(v01);
                v10 = tf32r(v10); v11 = tf32r(v11);
            }
            if (MODE == 0) {
                *(float2*)(C + (size_t)r0 * 1024 + c)       = make_float2(v00, v01);
                *(float2*)(C + (size_t)(r0 + 8) * 1024 + c) = make_float2(v10, v11);
            } else {
                const int h = c >> 6, d = c & 63;
                {
                    const int b = r0 >> 11, s_ = r0 & 2047;
                    *(float2*)(C + ((((size_t)(b * HEADS + h)) * Ss + s_) * HD + d))
                        = make_float2(v00, v01);
                }
                {
                    const int r1 = r0 + 8;
                    const int b = r1 >> 11, s_ = r1 & 2047;
                    *(float2*)(C + ((((size_t)(b * HEADS + h)) * Ss + s_) * HD + d))
                        = make_float2(v10, v11);
                }
            }
        }
    }
}

// ============================================================================
// Flash attention with tf32 mma.sync.
// Block = (bh, 128-query tile), 256 threads / 8 warps.
// QK warp tile 64x32 (wmq=wid&1, wnq=wid>>1); PV warp tile 32x32
// (wmp=wid&3, wnp=wid>>2). Smem-scan online softmax (128 threads).
// Strides: Q/K/V 68 (conflict-free frags), P 133 (CF scan, <=2-way frags).
// ============================================================================
#define AQSTR 68
#define APSTR 133
#define ATT_SMEM_FLOATS (3*128*AQSTR + 128*APSTR + 3*128)
#define ATT_SMEM_BYTES  (ATT_SMEM_FLOATS * 4)

__global__ __launch_bounds__(256, 1)
void attn_kernel()
{
    extern __shared__ float sm[];
    float* Qs   = sm;                      // 128*68
    float* Ks   = Qs + 128 * AQSTR;
    float* Vs   = Ks + 128 * AQSTR;
    float* Ps   = Vs + 128 * AQSTR;        // 128*133
    float* mrow = Ps + 128 * APSTR;
    float* lrow = mrow + 128;
    float* crow = lrow + 128;

    const int bh   = blockIdx.y;
    const int qt   = blockIdx.x;
    const int tid  = threadIdx.x;
    const int wid  = tid >> 5;
    const int lane = tid & 31;
    const int gr   = lane >> 2;
    const int tc   = lane & 3;
    const int wmq  = wid & 1,  wnq = wid >> 1;   // QK: 64x32
    const int wmp  = wid & 3,  wnp = wid >> 2;   // PV: 32x32

    const float* Qg = g_Q + (size_t)bh * Ss * HD + (size_t)qt * 128 * HD;
    const float* Kg = g_K + (size_t)bh * Ss * HD;
    const float* Vg = g_V + (size_t)bh * Ss * HD;

    // load Q tile (128x64) into stride-68 smem
    for (int f = tid; f < 2048; f += 256) {
        int r  = f >> 4;
        int c4 = (f & 15) << 2;
        float4 v = *(const float4*)(Qg + (size_t)r * HD + c4);
        float* q = Qs + r * AQSTR + c4;
        q[0] = v.x; q[1] = v.y; q[2] = v.z; q[3] = v.w;
    }
    if (tid < 128) { mrow[tid] = -1e30f; lrow[tid] = 0.f; }

    float o[2][4][4];
    #pragma unroll
    for (int mt = 0; mt < 2; mt++)
        #pragma unroll
        for (int nt = 0; nt < 4; nt++)
            #pragma unroll
            for (int e = 0; e < 4; e++) o[mt][nt][e] = 0.f;

    for (int kt = 0; kt < 16; kt++) {
        __syncthreads();   // prior QK/PV reads of Ks/Vs/Ps done

        const float* Kt = Kg + (size_t)kt * 128 * HD;
        const float* Vt = Vg + (size_t)kt * 128 * HD;
        for (int f = tid; f < 2048; f += 256) {
            int r  = f >> 4;
            int c4 = (f & 15) << 2;
            float4 kv = *(const float4*)(Kt + (size_t)r * HD + c4);
            float* kp = Ks + r * AQSTR + c4;
            kp[0] = kv.x; kp[1] = kv.y; kp[2] = kv.z; kp[3] = kv.w;
            float4 vv = *(const float4*)(Vt + (size_t)r * HD + c4);
            float* vp = Vs + r * AQSTR + c4;
            vp[0] = vv.x; vp[1] = vv.y; vp[2] = vv.z; vp[3] = vv.w;
        }
        __syncthreads();

        // ---- S = Q K^T (K=64, 8 ksteps), warp tile 64x32 ----
        float sacc[4][4][4];
        #pragma unroll
        for (int mt = 0; mt < 4; mt++)
            #pragma unroll
            for (int nt = 0; nt < 4; nt++)
                #pragma unroll
                for (int e = 0; e < 4; e++) sacc[mt][nt][e] = 0.f;

        #pragma unroll
        for (int ks = 0; ks < 8; ks++) {
            const int k0 = ks * 8;
            uint32_t a[4][4], b[4][2];
            #pragma unroll
            for (int mt = 0; mt < 4; mt++) {
                const float* p = Qs + (wmq * 64 + mt * 16 + gr) * AQSTR + k0 + tc;
                a[mt][0] = __float_as_uint(p[0]);
                a[mt][1] = __float_as_uint(p[8 * AQSTR]);
                a[mt][2] = __float_as_uint(p[4]);
                a[mt][3] = __float_as_uint(p[8 * AQSTR + 4]);
            }
            #pragma unroll
            for (int nt = 0; nt < 4; nt++) {
                const float* p = Ks + (wnq * 32 + nt * 8 + gr) * AQSTR + k0 + tc;
                b[nt][0] = __float_as_uint(p[0]);
                b[nt][1] = __float_as_uint(p[4]);
            }
            #pragma unroll
            for (int mt = 0; mt < 4; mt++)
                #pragma unroll
                for (int nt = 0; nt < 4; nt++)
                    mma8(sacc[mt][nt][0], sacc[mt][nt][1], sacc[mt][nt][2], sacc[mt][nt][3],
                         a[mt][0], a[mt][1], a[mt][2], a[mt][3], b[nt][0], b[nt][1]);
        }

        // store S*scale to Ps
        #pragma unroll
        for (int mt = 0; mt < 4; mt++) {
            const int r0 = wmq * 64 + mt * 16 + gr;
            #pragma unroll
            for (int nt = 0; nt < 4; nt++) {
                const int c = wnq * 32 + nt * 8 + 2 * tc;
                Ps[r0 * APSTR + c]           = sacc[mt][nt][0] * 0.125f;
                Ps[r0 * APSTR + c + 1]       = sacc[mt][nt][1] * 0.125f;
                Ps[(r0 + 8) * APSTR + c]     = sacc[mt][nt][2] * 0.125f;
                Ps[(r0 + 8) * APSTR + c + 1] = sacc[mt][nt][3] * 0.125f;
            }
        }
        __syncthreads();

        // ---- online softmax: 128 threads, one row each ----
        if (tid < 128) {
            float* pr = Ps + tid * APSTR;
            float mx = mrow[tid];
            #pragma unroll 4
            for (int k = 0; k < 128; k++) mx = fmaxf(mx, pr[k]);
            float corr = __expf(mrow[tid] - mx);
            float sum  = lrow[tid] * corr;
            #pragma unroll 4
            for (int k = 0; k < 128; k++) {
                float p = __expf(pr[k] - mx);
                sum += p;
                pr[k] = tf32r(p);
            }
            mrow[tid] = mx;
            lrow[tid] = sum;
            crow[tid] = corr;
        }
        __syncthreads();

        // ---- rescale o, then o += P V (K=128, 16 ksteps), warp tile 32x32 ----
        #pragma unroll
        for (int mt = 0; mt < 2; mt++) {
            const int r0 = wmp * 32 + mt * 16 + gr;
            const float c0 = crow[r0];
            const float c1 = crow[r0 + 8];
            #pragma unroll
            for (int nt = 0; nt < 4; nt++) {
                o[mt][nt][0] *= c0; o[mt][nt][1] *= c0;
                o[mt][nt][2] *= c1; o[mt][nt][3] *= c1;
            }
        }
        #pragma unroll 4
        for (int ks = 0; ks < 16; ks++) {
            const int k0 = ks * 8;
            uint32_t a[2][4], b[4][2];
            #pragma unroll
            for (int mt = 0; mt < 2; mt++) {
                const float* p = Ps + (wmp * 32 + mt * 16 + gr) * APSTR + k0 + tc;
                a[mt][0] = __float_as_uint(p[0]);
                a[mt][1] = __float_as_uint(p[8 * APSTR]);
                a[mt][2] = __float_as_uint(p[4]);
                a[mt][3] = __float_as_uint(p[8 * APSTR + 4]);
            }
            #pragma unroll
            for (int nt = 0; nt < 4; nt++) {
                const float* p = Vs + (k0 + tc) * AQSTR + wnp * 32 + nt * 8 + gr;
                b[nt][0] = __float_as_uint(p[0]);
                b[nt][1] = __float_as_uint(p[4 * AQSTR]);
            }
            #pragma unroll
            for (int mt = 0; mt < 2; mt++)
                #pragma unroll
                for (int nt = 0; nt < 4; nt++)
                    mma8(o[mt][nt][0], o[mt][nt][1], o[mt][nt][2], o[mt][nt][3],
                         a[mt][0], a[mt][1], a[mt][2], a[mt][3], b[nt][0], b[nt][1]);
        }
    }

    // ---- normalize + store to g_O [B,S,H*D] ----
    const int b = bh >> 4;
    const int h = bh & 15;
    #pragma unroll
    for (int mt = 0; mt < 2; mt++) {
        const int r0 = wmp * 32 + mt * 16 + gr;
        const float i0 = 1.0f / lrow[r0];
        const float i1 = 1.0f / lrow[r0 + 8];
        #pragma unroll
        for (int nt = 0; nt < 4; nt++) {
            const int c = wnp * 32 + nt * 8 + 2 * tc;   // d index
            {
                const int s_ = qt * 128 + r0;
                size_t idx = ((size_t)(b * Ss + s_)) * HIDn + h * HD + c;
                *(float2*)(g_O + idx) = make_float2(o[mt][nt][0] * i0, o[mt][nt][1] * i0);
            }
            {
                const int s_ = qt * 128 + r0 + 8;
                size_t idx = ((size_t)(b * Ss + s_)) * HIDn + h * HD + c;
                *(float2*)(g_O + idx) = make_float2(o[mt][nt][2] * i1, o[mt][nt][3] * i1);
            }
        }
    }
}

// ============================================================================
// launch
// ============================================================================
extern "C" void kernel_launch(void* const* d_in, const int* in_sizes, int n_in,
                              void* d_out, int out_size)
{
    (void)in_sizes; (void)n_in; (void)out_size;
    const float* q  = (const float*)d_in[0];
    const float* k  = (const float*)d_in[1];
    const float* v  = (const float*)d_in[2];
    const float* wq = (const float*)d_in[3];
    const float* bq = (const float*)d_in[4];
    const float* wk = (const float*)d_in[5];
    const float* bk = (const float*)d_in[6];
    const float* wv = (const float*)d_in[7];
    const float* bv = (const float*)d_in[8];
    const float* wo = (const float*)d_in[9];
    const float* bo = (const float*)d_in[10];
    float* out = (float*)d_out;

    float *Qp, *Kp, *Vp, *Op, *WTp;
    cudaGetSymbolAddress((void**)&Qp,  g_Q);
    cudaGetSymbolAddress((void**)&Kp,  g_K);
    cudaGetSymbolAddress((void**)&Vp,  g_V);
    cudaGetSymbolAddress((void**)&Op,  g_O);
    cudaGetSymbolAddress((void**)&WTp, g_WT);

    cudaFuncSetAttribute(attn_kernel,
                         cudaFuncAttributeMaxDynamicSharedMemorySize, ATT_SMEM_BYTES);
    cudaFuncSetAttribute(gemm_tc<0>,
                         cudaFuncAttributeMaxDynamicSharedMemorySize, GEMM_SMEM);
    cudaFuncSetAttribute(gemm_tc<1>,
                         cudaFuncAttributeMaxDynamicSharedMemorySize, GEMM_SMEM);

    dim3 tgrid(32, 32), tblk(32, 8);
    dim3 ggrid(HIDn / 128, ROWS / 128);   // (8, 64)

    transpose1024<<<tgrid, tblk>>>(wq, WTp);
    gemm_tc<1><<<ggrid, 256, GEMM_SMEM>>>(q, WTp, bq, Qp);
    transpose1024<<<tgrid, tblk>>>(wk, WTp);
    gemm_tc<1><<<ggrid, 256, GEMM_SMEM>>>(k, WTp, bk, Kp);
    transpose1024<<<tgrid, tblk>>>(wv, WTp);
    gemm_tc<1><<<ggrid, 256, GEMM_SMEM>>>(v, WTp, bv, Vp);

    attn_kernel<<<dim3(Ss / 128, Bb * HEADS), 256, ATT_SMEM_BYTES>>>();

    transpose1024<<<tgrid, tblk>>>(wo, WTp);
    gemm_tc<0><<<ggrid, 256, GEMM_SMEM>>>(Op, WTp, bo, out);
}